// round 13
// baseline (speedup 1.0000x reference)
#include <cuda_runtime.h>
#include <math.h>
#include <stdint.h>

#define NB      8192
#define TILE_B  28
#define NT      512
#define GRID    293
#define MPAD    32

// padded leading dims (all == 4 mod 32 -> conflict-free fragment LDS)
#define LDH 132
#define LDX 68
#define LDZ 260
#define LDB 68

// smem (floats): header 240 | h 32x132 @240 | x 32x68 @4464 | z 32x260 @6640 (z1, then z2 in-place)
// blog aliases x (dead after z1 phase)
#define OFF_H    240
#define OFF_X    4464
#define OFF_Z    6640
#define OFF_BLOG 4464
#define SMEM_FLOATS 14960

__device__ __forceinline__ float silu_f(float x){
    return x * (1.0f / (1.0f + __expf(-x)));
}

// m16n8k8 tf32 mma: D += A*B (fp32 accum). Raw fp32 bits as tf32 (HW truncation).
__device__ __forceinline__ void mma_tf32(float* d, const uint32_t* a, uint32_t b0, uint32_t b1){
    asm volatile(
        "mma.sync.aligned.m16n8k8.row.col.f32.tf32.tf32.f32 "
        "{%0,%1,%2,%3}, {%4,%5,%6,%7}, {%8,%9}, {%0,%1,%2,%3};"
        : "+f"(d[0]), "+f"(d[1]), "+f"(d[2]), "+f"(d[3])
        : "r"(a[0]), "r"(a[1]), "r"(a[2]), "r"(a[3]), "r"(b0), "r"(b1));
}

// Warp-level GEMM phase. A in smem (LDA_), B in gmem row-major [K x LDN_], D to smem (LDD_).
// NRT row-tiles starting at rt0; NTILES n8-tiles starting at col n0.
// INPLACE: __syncthreads() between final A-read (accumulation) and D-write (D may alias A).
template<int KSTEPS, int NTILES, int NRT, int LDA_, int LDN_, int LDD_, bool DOSILU, bool INPLACE>
__device__ __forceinline__ void mma_phase(const float* __restrict__ As,
                                          const float* __restrict__ Bg,
                                          const float* __restrict__ bias,
                                          float* __restrict__ Ds,
                                          int n0, int rt0, int lane)
{
    const int gid = lane >> 2, tig = lane & 3;
    float d[NRT][NTILES][4];
    #pragma unroll
    for (int rt = 0; rt < NRT; rt++)
        #pragma unroll
        for (int nt = 0; nt < NTILES; nt++)
            #pragma unroll
            for (int i = 0; i < 4; i++) d[rt][nt][i] = 0.f;

    #pragma unroll 4
    for (int ks = 0; ks < KSTEPS; ks++){
        const int k0 = ks * 8;
        uint32_t a[NRT][4];
        #pragma unroll
        for (int rt = 0; rt < NRT; rt++){
            const int r = gid + 16 * (rt0 + rt);
            a[rt][0] = __float_as_uint(As[r       * LDA_ + k0 + tig]);
            a[rt][1] = __float_as_uint(As[(r + 8) * LDA_ + k0 + tig]);
            a[rt][2] = __float_as_uint(As[r       * LDA_ + k0 + tig + 4]);
            a[rt][3] = __float_as_uint(As[(r + 8) * LDA_ + k0 + tig + 4]);
        }
        #pragma unroll
        for (int nt = 0; nt < NTILES; nt++){
            const float* Bp = Bg + (size_t)(k0 + tig) * LDN_ + n0 + nt * 8 + gid;
            uint32_t b0 = __float_as_uint(Bp[0]);
            uint32_t b1 = __float_as_uint(Bp[4 * LDN_]);
            #pragma unroll
            for (int rt = 0; rt < NRT; rt++)
                mma_tf32(d[rt][nt], a[rt], b0, b1);
        }
    }
    if (INPLACE) __syncthreads();
    #pragma unroll
    for (int rt = 0; rt < NRT; rt++){
        #pragma unroll
        for (int nt = 0; nt < NTILES; nt++){
            const int r = gid + 16 * (rt0 + rt);
            const int c = n0 + nt * 8 + 2 * tig;
            const float bx = bias[c], by = bias[c + 1];
            float v0 = d[rt][nt][0] + bx, v1 = d[rt][nt][1] + by;
            float v2 = d[rt][nt][2] + bx, v3 = d[rt][nt][3] + by;
            if (DOSILU){ v0 = silu_f(v0); v1 = silu_f(v1); v2 = silu_f(v2); v3 = silu_f(v3); }
            *reinterpret_cast<float2*>(Ds + r       * LDD_ + c) = make_float2(v0, v1);
            *reinterpret_cast<float2*>(Ds + (r + 8) * LDD_ + c) = make_float2(v2, v3);
        }
    }
}

// Warp-cooperative top-6 of 64 values (2 per lane). Tie-break: lower index.
__device__ __forceinline__ void topk6(float p0, float p1, int lane, int* sel, float* sv){
    #pragma unroll
    for (int t = 0; t < 6; ++t){
        float v = p0; int id = lane;
        if (p1 > v){ v = p1; id = lane + 32; }
        #pragma unroll
        for (int off = 16; off > 0; off >>= 1){
            float ov = __shfl_xor_sync(0xffffffffu, v, off);
            int  oid = __shfl_xor_sync(0xffffffffu, id, off);
            if (ov > v || (ov == v && oid < id)){ v = ov; id = oid; }
        }
        sv[t] = v; sel[t] = id;
        if (id == lane)           p0 = -INFINITY;
        else if (id == lane + 32) p1 = -INFINITY;
    }
}

// One row: gumbel perturb, top-5 select, one-hot write, exact-PL log-prob.
__device__ float row_topk_lp(const float* __restrict__ u,
                             const float* __restrict__ lg,
                             float m, float Z,
                             float* __restrict__ cfg,
                             int lane, int* selOut)
{
    float l0 = lg[lane], l1 = lg[lane + 32];
    float u0 = fmaxf(u[lane],      1e-10f);
    float u1 = fmaxf(u[lane + 32], 1e-10f);
    float p0 = l0 - __logf(-__logf(u0));
    float p1 = l1 - __logf(-__logf(u1));
    int sel[6]; float sv[6];
    topk6(p0, p1, lane, sel, sv);
    if (sv[4] - sv[5] < 1e-4f){
        p0 = l0 - (float)log(-log((double)u0));
        p1 = l1 - (float)log(-log((double)u1));
        topk6(p0, p1, lane, sel, sv);
    }
    float c0 = 0.f, c1 = 0.f;
    #pragma unroll
    for (int t = 0; t < 5; ++t){
        c0 += (sel[t] == lane)      ? 1.f : 0.f;
        c1 += (sel[t] == lane + 32) ? 1.f : 0.f;
    }
    cfg[lane]      = c0;
    cfg[lane + 32] = c1;

    // exact PL over 5! orderings via 2^5-subset DP
    float lsum = 0.f, e[5];
    #pragma unroll
    for (int t = 0; t < 5; ++t){
        float lt = lg[sel[t]];
        lsum += lt;
        e[t] = expf(lt - m);
    }
    float f[32];
    f[31] = 1.f;
    #pragma unroll
    for (int mask = 30; mask >= 0; --mask){
        float Em = 0.f, s = 0.f;
        #pragma unroll
        for (int t = 0; t < 5; ++t){
            if (mask & (1 << t)) Em += e[t];
            else                 s  += f[mask | (1 << t)];
        }
        f[mask] = __fdividef(s, Z - Em);
    }
    #pragma unroll
    for (int t = 0; t < 5; ++t) selOut[t] = sel[t];
    return lsum - 5.f * m + logf(f[0]);
}

__global__ __launch_bounds__(NT, 2)
void pcf_kernel(const float* __restrict__ Ua, const float* __restrict__ Ub,
                const float* __restrict__ AL,
                const float* __restrict__ W1, const float* __restrict__ b1,
                const float* __restrict__ W2, const float* __restrict__ b2,
                const float* __restrict__ V1, const float* __restrict__ c1,
                const float* __restrict__ V2, const float* __restrict__ c2,
                const float* __restrict__ V3, const float* __restrict__ c3,
                float* __restrict__ out)
{
    extern __shared__ float sm[];
    float* s_alog = sm;                    // 64
    float* s_scal = sm + 64;               // 4
    int*   s_sela = (int*)(sm + 68);       // 140 (28 rows x 5)
    float* s_lpa  = sm + 208;              // 28 -> header ends 240
    float* s_h    = sm + OFF_H;            // 32 x LDH (pad rows zero)
    float* s_x    = sm + OFF_X;            // 32 x LDX
    float* s_z    = sm + OFF_Z;            // 32 x LDZ (z1, then z2 in place)
    float* s_blog = sm + OFF_BLOG;         // aliases dead x

    const int tid  = threadIdx.x;
    const int lane = tid & 31;
    const int wid  = tid >> 5;             // 0..15
    const int row0 = blockIdx.x * TILE_B;

    // --- alpha logits stats (block-constant) ---
    if (wid == 0){
        float l0 = AL[lane], l1 = AL[lane + 32];
        s_alog[lane] = l0; s_alog[lane + 32] = l1;
        float mv = fmaxf(l0, l1);
        #pragma unroll
        for (int off = 16; off > 0; off >>= 1)
            mv = fmaxf(mv, __shfl_xor_sync(0xffffffffu, mv, off));
        float zv = expf(l0 - mv) + expf(l1 - mv);
        #pragma unroll
        for (int off = 16; off > 0; off >>= 1)
            zv += __shfl_xor_sync(0xffffffffu, zv, off);
        if (lane == 0){ s_scal[0] = mv; s_scal[1] = zv; }
    }
    __syncthreads();
    const float ma = s_scal[0], Za = s_scal[1];

    // --- alpha selection + lp_a (16 warps x 2 slots, clamped to 28 rows) ---
    for (int rr = 0; rr < 2; ++rr){
        int rloc = wid * 2 + rr;
        if (rloc > TILE_B - 1) rloc = TILE_B - 1;
        int row = row0 + rloc;
        if (row > NB - 1) row = NB - 1;
        int sel[5];
        float lp = row_topk_lp(Ua + (size_t)row * 64, s_alog, ma, Za,
                               out + (size_t)row * 128, lane, sel);
        if (lane == 0){
            s_lpa[rloc] = lp;
            #pragma unroll
            for (int t = 0; t < 5; ++t) s_sela[rloc * 5 + t] = sel[t];
        }
    }
    __syncthreads();

    // --- h = silu(sum of 5 W1 rows + b1), rows 28..31 zero-padded ---
    for (int i = tid; i < MPAD * 128; i += NT){
        int r = i >> 7, j = i & 127;
        float v = 0.f;
        if (r < TILE_B){
            float a = b1[j];
            #pragma unroll
            for (int t = 0; t < 5; ++t) a += W1[s_sela[r * 5 + t] * 128 + j];
            v = silu_f(a);
        }
        s_h[r * LDH + j] = v;
    }
    __syncthreads();

    // --- ctx = h @ W2 + b2 (M=32,N=64,K=128): warps split {row-tile x 8 n-slices} ---
    mma_phase<16, 1, 1, LDH, 64, LDX, false, false>(s_h, W2, b2, s_x,
                                                    (wid & 7) * 8, wid >> 3, lane);
    __syncthreads();

    // --- z1 = silu(ctx @ V1[64:,:] + c1) (M=32,N=256,K=64): each warp 16 cols, both row-tiles ---
    mma_phase<8, 2, 2, LDX, 256, LDZ, true, false>(s_x, V1 + 64 * 256, c1, s_z,
                                                   wid * 16, 0, lane);
    __syncthreads();

    // --- z2 = silu(z1 @ V2 + c2) (M=32,N=256,K=256): in-place over z1 (sync inside) ---
    mma_phase<32, 2, 2, LDZ, 256, LDZ, true, true>(s_z, V2, c2, s_z,
                                                   wid * 16, 0, lane);
    __syncthreads();

    // --- beta_logits = z2 @ V3 + c3 (M=32,N=64,K=256) ---
    mma_phase<32, 1, 1, LDZ, 64, LDB, false, false>(s_z, V3, c3, s_blog,
                                                    (wid & 7) * 8, wid >> 3, lane);
    __syncthreads();

    // --- beta selection + lp_b + final output (clamped slots) ---
    for (int rr = 0; rr < 2; ++rr){
        int rloc = wid * 2 + rr;
        if (rloc > TILE_B - 1) rloc = TILE_B - 1;
        int row = row0 + rloc;
        if (row > NB - 1) row = NB - 1;
        const float* lg = s_blog + rloc * LDB;
        float l0 = lg[lane], l1 = lg[lane + 32];
        float mv = fmaxf(l0, l1);
        #pragma unroll
        for (int off = 16; off > 0; off >>= 1)
            mv = fmaxf(mv, __shfl_xor_sync(0xffffffffu, mv, off));
        float zv = expf(l0 - mv) + expf(l1 - mv);
        #pragma unroll
        for (int off = 16; off > 0; off >>= 1)
            zv += __shfl_xor_sync(0xffffffffu, zv, off);
        int sel[5];
        float lpb = row_topk_lp(Ub + (size_t)row * 64, lg, mv, zv,
                                out + (size_t)row * 128 + 64, lane, sel);
        if (lane == 0)
            out[(size_t)NB * 128 + row] = s_lpa[rloc] + lpb;
    }
}

extern "C" void kernel_launch(void* const* d_in, const int* in_sizes, int n_in,
                              void* d_out, int out_size)
{
    (void)in_sizes; (void)n_in; (void)out_size;
    const float* Ua = (const float*)d_in[0];
    const float* Ub = (const float*)d_in[1];
    const float* AL = (const float*)d_in[2];
    const float* W1 = (const float*)d_in[3];
    const float* b1 = (const float*)d_in[4];
    const float* W2 = (const float*)d_in[5];
    const float* b2 = (const float*)d_in[6];
    const float* V1 = (const float*)d_in[7];
    const float* c1 = (const float*)d_in[8];
    const float* V2 = (const float*)d_in[9];
    const float* c2 = (const float*)d_in[10];
    const float* V3 = (const float*)d_in[11];
    const float* c3 = (const float*)d_in[12];
    float* out = (float*)d_out;

    const int smem_bytes = SMEM_FLOATS * (int)sizeof(float);
    cudaFuncSetAttribute(pcf_kernel, cudaFuncAttributeMaxDynamicSharedMemorySize, smem_bytes);
    pcf_kernel<<<GRID, NT, smem_bytes>>>(Ua, Ub, AL, W1, b1, W2, b2,
                                         V1, c1, V2, c2, V3, c3, out);
}

// round 17
// speedup vs baseline: 1.5133x; 1.5133x over previous
#include <cuda_runtime.h>
#include <cuda_bf16.h>
#include <math.h>
#include <stdint.h>

#define NB      8192
#define TILE_B  28
#define NT      512
#define GRID    293
#define MPAD    32

// bf16 leading dims (elements); all strides*2 == 16 mod 128 -> LDSM conflict-free
#define LDH_BF 136
#define LDX_BF 72
#define LDZ_BF 264
#define LDB_F  68       // blog stays fp32

// smem byte offsets
#define OFFB_ALOG 0
#define OFFB_SCAL 256
#define OFFB_SELA 272
#define OFFB_LPA  832
#define OFF_H     960
#define OFF_X     9664
#define OFF_Z     14272
#define OFF_BLOG  31168
#define SMEM_BYTES 39872

// packed B fragment buffers: [(nt*KS + ks)*32 + lane] -> uint2 {b0,b1}
__device__ uint2 g_W2p[8  * 8  * 32];   // N=64,  K=128
__device__ uint2 g_V1p[32 * 4  * 32];   // N=256, K=64  (V1 rows 64..127)
__device__ uint2 g_V2p[32 * 16 * 32];   // N=256, K=256
__device__ uint2 g_V3p[8  * 16 * 32];   // N=64,  K=256

__device__ __forceinline__ float silu_f(float x){
    return x * (1.0f / (1.0f + __expf(-x)));
}

__device__ __forceinline__ uint32_t packbf2(float lo, float hi){
    __nv_bfloat162 p = __floats2bfloat162_rn(lo, hi);
    return *reinterpret_cast<uint32_t*>(&p);
}

__device__ __forceinline__ void mma_bf16(float* d, const uint32_t* a, uint32_t b0, uint32_t b1){
    asm volatile(
        "mma.sync.aligned.m16n8k16.row.col.f32.bf16.bf16.f32 "
        "{%0,%1,%2,%3}, {%4,%5,%6,%7}, {%8,%9}, {%0,%1,%2,%3};"
        : "+f"(d[0]), "+f"(d[1]), "+f"(d[2]), "+f"(d[3])
        : "r"(a[0]), "r"(a[1]), "r"(a[2]), "r"(a[3]), "r"(b0), "r"(b1));
}

__device__ __forceinline__ void ldsm_x4(uint32_t* a, uint32_t addr){
    asm volatile("ldmatrix.sync.aligned.m8n8.x4.shared.b16 {%0,%1,%2,%3}, [%4];"
        : "=r"(a[0]), "=r"(a[1]), "=r"(a[2]), "=r"(a[3]) : "r"(addr));
}

// ---- weight pre-pack kernel: fp32 W[K x N] -> bf16 mma B-fragments ----
__global__ void pack_weights(const float* __restrict__ W2, const float* __restrict__ V1s,
                             const float* __restrict__ V2, const float* __restrict__ V3)
{
    int gid = blockIdx.x * blockDim.x + threadIdx.x;
    const float* src; uint2* dst; int N, KS, idx;
    if      (gid < 2048){  src = W2;  dst = g_W2p; N = 64;  KS = 8;  idx = gid; }
    else if (gid < 6144){  src = V1s; dst = g_V1p; N = 256; KS = 4;  idx = gid - 2048; }
    else if (gid < 22528){ src = V2;  dst = g_V2p; N = 256; KS = 16; idx = gid - 6144; }
    else if (gid < 26624){ src = V3;  dst = g_V3p; N = 64;  KS = 16; idx = gid - 22528; }
    else return;
    int nt = idx / (KS * 32); int rem = idx % (KS * 32);
    int ks = rem >> 5, lane = rem & 31;
    int g = lane >> 2, t = lane & 3;
    int n = nt * 8 + g, k0 = ks * 16;
    uint2 v;
    v.x = packbf2(src[(k0 + 2*t    ) * N + n], src[(k0 + 2*t + 1) * N + n]);
    v.y = packbf2(src[(k0 + 2*t + 8) * N + n], src[(k0 + 2*t + 9) * N + n]);
    dst[idx] = v;
}

// ---- warp-level bf16 GEMM phase ----
// A: bf16 smem (byte addr aBase, ld LDA_BF elems); B: packed gmem fragments; D: smem.
template<int KS, int NTILES, int NRT, int LDA_BF, bool DOSILU, bool DEST_BF16, bool INPLACE, int LDD_>
__device__ __forceinline__ void mma_phase_bf(uint32_t aBase,
                                             const uint2* __restrict__ Bpack,
                                             const float* __restrict__ bias,
                                             void* __restrict__ Ds,
                                             int n0, int rt0, int lane)
{
    const int gid = lane >> 2, tig = lane & 3;
    uint32_t a_addr[NRT];
    {
        int lrow = (lane & 7) + ((lane >> 3) & 1) * 8;
        int kofs = (lane >> 4) * 8;
        #pragma unroll
        for (int rt = 0; rt < NRT; rt++)
            a_addr[rt] = aBase + (uint32_t)(((((rt0 + rt) * 16 + lrow) * LDA_BF) + kofs) * 2);
    }
    float d[NRT][NTILES][4];
    #pragma unroll
    for (int rt = 0; rt < NRT; rt++)
        #pragma unroll
        for (int nt = 0; nt < NTILES; nt++)
            #pragma unroll
            for (int i = 0; i < 4; i++) d[rt][nt][i] = 0.f;

    #pragma unroll 4
    for (int ks = 0; ks < KS; ks++){
        uint32_t a[NRT][4];
        #pragma unroll
        for (int rt = 0; rt < NRT; rt++)
            ldsm_x4(a[rt], a_addr[rt] + ks * 32);
        #pragma unroll
        for (int nt = 0; nt < NTILES; nt++){
            uint2 bv = Bpack[(size_t)(((n0 >> 3) + nt) * KS + ks) * 32 + lane];
            #pragma unroll
            for (int rt = 0; rt < NRT; rt++)
                mma_bf16(d[rt][nt], a[rt], bv.x, bv.y);
        }
    }
    if (INPLACE) __syncthreads();
    #pragma unroll
    for (int rt = 0; rt < NRT; rt++){
        #pragma unroll
        for (int nt = 0; nt < NTILES; nt++){
            const int r = gid + 16 * (rt0 + rt);
            const int c = n0 + nt * 8 + 2 * tig;
            const float bx = bias[c], by = bias[c + 1];
            float v0 = d[rt][nt][0] + bx, v1 = d[rt][nt][1] + by;
            float v2 = d[rt][nt][2] + bx, v3 = d[rt][nt][3] + by;
            if (DOSILU){ v0 = silu_f(v0); v1 = silu_f(v1); v2 = silu_f(v2); v3 = silu_f(v3); }
            if (DEST_BF16){
                uint32_t* D = (uint32_t*)Ds;
                D[(r       * LDD_ + c) >> 1] = packbf2(v0, v1);
                D[((r + 8) * LDD_ + c) >> 1] = packbf2(v2, v3);
            } else {
                float* D = (float*)Ds;
                *reinterpret_cast<float2*>(D + r       * LDD_ + c) = make_float2(v0, v1);
                *reinterpret_cast<float2*>(D + (r + 8) * LDD_ + c) = make_float2(v2, v3);
            }
        }
    }
}

// Warp-cooperative top-6 of 64 values (2 per lane). Tie-break: lower index.
__device__ __forceinline__ void topk6(float p0, float p1, int lane, int* sel, float* sv){
    #pragma unroll
    for (int t = 0; t < 6; ++t){
        float v = p0; int id = lane;
        if (p1 > v){ v = p1; id = lane + 32; }
        #pragma unroll
        for (int off = 16; off > 0; off >>= 1){
            float ov = __shfl_xor_sync(0xffffffffu, v, off);
            int  oid = __shfl_xor_sync(0xffffffffu, id, off);
            if (ov > v || (ov == v && oid < id)){ v = ov; id = oid; }
        }
        sv[t] = v; sel[t] = id;
        if (id == lane)           p0 = -INFINITY;
        else if (id == lane + 32) p1 = -INFINITY;
    }
}

// One row: gumbel perturb, top-5 select, one-hot write, exact-PL log-prob.
__device__ float row_topk_lp(const float* __restrict__ u,
                             const float* __restrict__ lg,
                             float m, float Z,
                             float* __restrict__ cfg,
                             int lane, int* selOut)
{
    float l0 = lg[lane], l1 = lg[lane + 32];
    float u0 = fmaxf(u[lane],      1e-10f);
    float u1 = fmaxf(u[lane + 32], 1e-10f);
    float p0 = l0 - __logf(-__logf(u0));
    float p1 = l1 - __logf(-__logf(u1));
    int sel[6]; float sv[6];
    topk6(p0, p1, lane, sel, sv);
    if (sv[4] - sv[5] < 1e-4f){
        p0 = l0 - (float)log(-log((double)u0));
        p1 = l1 - (float)log(-log((double)u1));
        topk6(p0, p1, lane, sel, sv);
    }
    float c0 = 0.f, c1 = 0.f;
    #pragma unroll
    for (int t = 0; t < 5; ++t){
        c0 += (sel[t] == lane)      ? 1.f : 0.f;
        c1 += (sel[t] == lane + 32) ? 1.f : 0.f;
    }
    cfg[lane]      = c0;
    cfg[lane + 32] = c1;

    float lsum = 0.f, e[5];
    #pragma unroll
    for (int t = 0; t < 5; ++t){
        float lt = lg[sel[t]];
        lsum += lt;
        e[t] = expf(lt - m);
    }
    float f[32];
    f[31] = 1.f;
    #pragma unroll
    for (int mask = 30; mask >= 0; --mask){
        float Em = 0.f, s = 0.f;
        #pragma unroll
        for (int t = 0; t < 5; ++t){
            if (mask & (1 << t)) Em += e[t];
            else                 s  += f[mask | (1 << t)];
        }
        f[mask] = __fdividef(s, Z - Em);
    }
    #pragma unroll
    for (int t = 0; t < 5; ++t) selOut[t] = sel[t];
    return lsum - 5.f * m + logf(f[0]);
}

__global__ __launch_bounds__(NT, 2)
void pcf_kernel(const float* __restrict__ Ua, const float* __restrict__ Ub,
                const float* __restrict__ AL,
                const float* __restrict__ W1, const float* __restrict__ b1,
                const float* __restrict__ b2, const float* __restrict__ c1,
                const float* __restrict__ c2, const float* __restrict__ c3,
                float* __restrict__ out)
{
    extern __shared__ __align__(16) char smraw[];
    float* s_alog = (float*)(smraw + OFFB_ALOG);
    float* s_scal = (float*)(smraw + OFFB_SCAL);
    int*   s_sela = (int*)  (smraw + OFFB_SELA);
    float* s_lpa  = (float*)(smraw + OFFB_LPA);
    uint32_t* s_h32 = (uint32_t*)(smraw + OFF_H);
    float* s_blog = (float*)(smraw + OFF_BLOG);

    const uint32_t sbase = (uint32_t)__cvta_generic_to_shared(smraw);
    const uint32_t aH = sbase + OFF_H, aX = sbase + OFF_X, aZ = sbase + OFF_Z;

    const int tid  = threadIdx.x;
    const int lane = tid & 31;
    const int wid  = tid >> 5;             // 0..15
    const int row0 = blockIdx.x * TILE_B;

    // --- alpha logits stats (block-constant) ---
    if (wid == 0){
        float l0 = AL[lane], l1 = AL[lane + 32];
        s_alog[lane] = l0; s_alog[lane + 32] = l1;
        float mv = fmaxf(l0, l1);
        #pragma unroll
        for (int off = 16; off > 0; off >>= 1)
            mv = fmaxf(mv, __shfl_xor_sync(0xffffffffu, mv, off));
        float zv = expf(l0 - mv) + expf(l1 - mv);
        #pragma unroll
        for (int off = 16; off > 0; off >>= 1)
            zv += __shfl_xor_sync(0xffffffffu, zv, off);
        if (lane == 0){ s_scal[0] = mv; s_scal[1] = zv; }
    }
    __syncthreads();
    const float ma = s_scal[0], Za = s_scal[1];

    // --- alpha selection + lp_a (16 warps x 2 slots, clamped) ---
    for (int rr = 0; rr < 2; ++rr){
        int rloc = wid * 2 + rr;
        if (rloc > TILE_B - 1) rloc = TILE_B - 1;
        int row = row0 + rloc;
        if (row > NB - 1) row = NB - 1;
        int sel[5];
        float lp = row_topk_lp(Ua + (size_t)row * 64, s_alog, ma, Za,
                               out + (size_t)row * 128, lane, sel);
        if (lane == 0){
            s_lpa[rloc] = lp;
            #pragma unroll
            for (int t = 0; t < 5; ++t) s_sela[rloc * 5 + t] = sel[t];
        }
    }
    __syncthreads();

    // --- h = silu(sum of 5 W1 rows + b1) -> bf16 pairs; rows 28..31 zero ---
    for (int i = tid; i < MPAD * 64; i += NT){
        int r = i >> 6, jp = i & 63;
        uint32_t val = 0;
        if (r < TILE_B){
            float2 a = *(const float2*)(b1 + 2 * jp);
            #pragma unroll
            for (int t = 0; t < 5; ++t){
                const float2 w = *(const float2*)(W1 + s_sela[r * 5 + t] * 128 + 2 * jp);
                a.x += w.x; a.y += w.y;
            }
            val = packbf2(silu_f(a.x), silu_f(a.y));
        }
        s_h32[r * (LDH_BF / 2) + jp] = val;
    }
    __syncthreads();

    // --- ctx = h @ W2 + b2 (M=32,N=64,K=128) -> x (bf16) ---
    mma_phase_bf<8, 1, 1, LDH_BF, false, true, false, LDX_BF>(
        aH, g_W2p, b2, (void*)(smraw + OFF_X), (wid & 7) * 8, wid >> 3, lane);
    __syncthreads();

    // --- z1 = silu(ctx @ V1[64:,:] + c1) (M=32,N=256,K=64) -> z (bf16) ---
    mma_phase_bf<4, 2, 2, LDX_BF, true, true, false, LDZ_BF>(
        aX, g_V1p, c1, (void*)(smraw + OFF_Z), wid * 16, 0, lane);
    __syncthreads();

    // --- z2 = silu(z1 @ V2 + c2) (M=32,N=256,K=256) in-place over z1 ---
    mma_phase_bf<16, 2, 2, LDZ_BF, true, true, true, LDZ_BF>(
        aZ, g_V2p, c2, (void*)(smraw + OFF_Z), wid * 16, 0, lane);
    __syncthreads();

    // --- beta_logits = z2 @ V3 + c3 (M=32,N=64,K=256) -> blog (fp32) ---
    mma_phase_bf<16, 1, 1, LDZ_BF, false, false, false, LDB_F>(
        aZ, g_V3p, c3, (void*)s_blog, (wid & 7) * 8, wid >> 3, lane);
    __syncthreads();

    // --- beta selection + lp_b + final output (clamped slots) ---
    for (int rr = 0; rr < 2; ++rr){
        int rloc = wid * 2 + rr;
        if (rloc > TILE_B - 1) rloc = TILE_B - 1;
        int row = row0 + rloc;
        if (row > NB - 1) row = NB - 1;
        const float* lg = s_blog + rloc * LDB_F;
        float l0 = lg[lane], l1 = lg[lane + 32];
        float mv = fmaxf(l0, l1);
        #pragma unroll
        for (int off = 16; off > 0; off >>= 1)
            mv = fmaxf(mv, __shfl_xor_sync(0xffffffffu, mv, off));
        float zv = expf(l0 - mv) + expf(l1 - mv);
        #pragma unroll
        for (int off = 16; off > 0; off >>= 1)
            zv += __shfl_xor_sync(0xffffffffu, zv, off);
        int sel[5];
        float lpb = row_topk_lp(Ub + (size_t)row * 64, lg, mv, zv,
                                out + (size_t)row * 128 + 64, lane, sel);
        if (lane == 0)
            out[(size_t)NB * 128 + row] = s_lpa[rloc] + lpb;
    }
}

extern "C" void kernel_launch(void* const* d_in, const int* in_sizes, int n_in,
                              void* d_out, int out_size)
{
    (void)in_sizes; (void)n_in; (void)out_size;
    const float* Ua = (const float*)d_in[0];
    const float* Ub = (const float*)d_in[1];
    const float* AL = (const float*)d_in[2];
    const float* W1 = (const float*)d_in[3];
    const float* b1 = (const float*)d_in[4];
    const float* W2 = (const float*)d_in[5];
    const float* b2 = (const float*)d_in[6];
    const float* V1 = (const float*)d_in[7];
    const float* c1 = (const float*)d_in[8];
    const float* V2 = (const float*)d_in[9];
    const float* c2 = (const float*)d_in[10];
    const float* V3 = (const float*)d_in[11];
    const float* c3 = (const float*)d_in[12];
    float* out = (float*)d_out;

    pack_weights<<<104, 256>>>(W2, V1 + 64 * 256, V2, V3);

    cudaFuncSetAttribute(pcf_kernel, cudaFuncAttributeMaxDynamicSharedMemorySize, SMEM_BYTES);
    pcf_kernel<<<GRID, NT, SMEM_BYTES>>>(Ua, Ub, AL, W1, b1, b2, c1, c2, c3, out);
}